// round 4
// baseline (speedup 1.0000x reference)
#include <cuda_runtime.h>
#include <math.h>

#define BATCH 64
#define LQ    1024
#define LK    1024
#define DD    64
#define RQ    16            // q rows per CTA
#define NTHR  256
#define SROW  1032          // padded S row stride (floats)
#define KTPAD 132           // transposed K tile row stride (floats)

// smem layout (floats):
//   S   [RQ][SROW]          = 16512
//   KV  max(64*132,128*64)  = 8448   (K tile transposed / V tile natural)
//   Qt  [64][RQ]            = 1024
//   rowstat [32]            = 32
#define SMEM_FLOATS (RQ * SROW + 8448 + 64 * RQ + 32)

__global__ void __launch_bounds__(NTHR, 2)
sdpa_fused_kernel(const float* __restrict__ q,
                  const float* __restrict__ k,
                  const float* __restrict__ v,
                  const int* __restrict__ mask,      // bool upconverted to int32 by harness
                  float* __restrict__ out,
                  float* __restrict__ attn)
{
    extern __shared__ float smem[];
    float* S       = smem;                       // RQ x SROW
    float* KV      = S + RQ * SROW;              // 8448 floats
    float* Qt      = KV + 8448;                  // 64 x RQ (transposed Q)
    float* rowstat = Qt + 64 * RQ;               // [0..15] = 1/l

    const int bx  = blockIdx.x;
    const int b   = bx >> 6;          // batch
    const int q0  = (bx & 63) * RQ;   // first q row of this tile
    const int tid = threadIdx.x;

    const float* Qg = q + ((size_t)b * LQ + q0) * DD;
    const float* Kg = k + (size_t)b * LK * DD;
    const float* Vg = v + (size_t)b * LK * DD;
    const int*   Mg = mask + ((size_t)b * LQ + q0) * (size_t)LK;

    // ---- stage Q transposed: Qt[d][r] ----
    for (int i = tid; i < RQ * DD; i += NTHR) {
        int r = i >> 6, d = i & 63;
        Qt[d * RQ + r] = Qg[i];
    }

    // =========================== GEMM 1: S = Q K^T ===========================
    // thread -> (qg, kg): 4 q rows x 2 k cols microtile
    const int qg = tid >> 6;          // 0..3
    const int kg = tid & 63;          // 0..63

    for (int kt = 0; kt < LK / 128; ++kt) {
        __syncthreads();  // previous tile consumers done (also orders Qt writes on kt=0)
        // stage 128x64 K tile transposed: KV[d][kk], padded stride KTPAD
        const float* Ksrc = Kg + (size_t)kt * 128 * DD;
        for (int i = tid; i < 128 * DD; i += NTHR) {
            int row = i >> 6, col = i & 63;
            KV[col * KTPAD + row] = Ksrc[i];
        }
        __syncthreads();

        float acc[4][2] = {{0.f,0.f},{0.f,0.f},{0.f,0.f},{0.f,0.f}};
        #pragma unroll 8
        for (int d = 0; d < DD; ++d) {
            float4 qv  = *(const float4*)&Qt[d * RQ + qg * 4];     // broadcast in warp
            float2 kv2 = *(const float2*)&KV[d * KTPAD + kg * 2];
            acc[0][0] += qv.x * kv2.x;  acc[0][1] += qv.x * kv2.y;
            acc[1][0] += qv.y * kv2.x;  acc[1][1] += qv.y * kv2.y;
            acc[2][0] += qv.z * kv2.x;  acc[2][1] += qv.z * kv2.y;
            acc[3][0] += qv.w * kv2.x;  acc[3][1] += qv.w * kv2.y;
        }

        // epilogue: scale by 1/8, apply mask (nonzero -> -1e9), store to S
        #pragma unroll
        for (int i = 0; i < 4; ++i) {
            int r    = qg * 4 + i;
            int kcol = kt * 128 + kg * 2;
            int2 m2  = *(const int2*)&Mg[(size_t)r * LK + kcol];
            float s0 = acc[i][0] * 0.125f;
            float s1 = acc[i][1] * 0.125f;
            if (m2.x) s0 = -1e9f;
            if (m2.y) s1 = -1e9f;
            S[r * SROW + kcol]     = s0;
            S[r * SROW + kcol + 1] = s1;
        }
    }
    __syncthreads();

    // =========================== softmax over LK ===========================
    {
        const int r = tid >> 4;       // 0..15
        const int t = tid & 15;       // 16 threads per row
        float m = -INFINITY;
        for (int kk = t; kk < LK; kk += 16)
            m = fmaxf(m, S[r * SROW + kk]);
        #pragma unroll
        for (int off = 8; off; off >>= 1)
            m = fmaxf(m, __shfl_xor_sync(0xffffffffu, m, off));

        float l = 0.f;
        for (int kk = t; kk < LK; kk += 16) {
            float e = __expf(S[r * SROW + kk] - m);
            S[r * SROW + kk] = e;
            l += e;
        }
        #pragma unroll
        for (int off = 8; off; off >>= 1)
            l += __shfl_xor_sync(0xffffffffu, l, off);
        if (t == 0) rowstat[r] = 1.f / l;
    }
    __syncthreads();

    // normalize P in smem + write attn output (vectorized)
    {
        float* attn_base = attn + ((size_t)b * LQ + q0) * (size_t)LK;
        for (int i = tid; i < RQ * LK / 4; i += NTHR) {
            int r  = i >> 8;            // 256 float4 per row
            int kk = (i & 255) << 2;
            float inv = rowstat[r];
            float4 e4 = *(float4*)&S[r * SROW + kk];
            e4.x *= inv; e4.y *= inv; e4.z *= inv; e4.w *= inv;
            *(float4*)&S[r * SROW + kk] = e4;
            *(float4*)&attn_base[(size_t)r * LK + kk] = e4;
        }
    }

    // =========================== GEMM 2: O = P V ===========================
    // thread -> (r2, dg): 1 q row x 4 d cols microtile, k unrolled by 4
    const int r2 = tid >> 4;          // 0..15
    const int dg = tid & 15;          // d = 4*dg
    float o0 = 0.f, o1 = 0.f, o2 = 0.f, o3 = 0.f;

    for (int vt = 0; vt < LK / 128; ++vt) {
        __syncthreads();  // previous KV consumers done
        const float* Vsrc = Vg + (size_t)vt * 128 * DD;
        for (int i = tid; i < 128 * DD / 4; i += NTHR)
            ((float4*)KV)[i] = ((const float4*)Vsrc)[i];
        __syncthreads();

        const float* Prow = &S[r2 * SROW + vt * 128];
        #pragma unroll 4
        for (int kk = 0; kk < 128; kk += 4) {
            float4 p4 = *(const float4*)&Prow[kk];
            const float* Vr = &KV[kk * DD + dg * 4];
            float4 v0 = *(const float4*)&Vr[0];
            float4 v1 = *(const float4*)&Vr[DD];
            float4 v2 = *(const float4*)&Vr[2 * DD];
            float4 v3 = *(const float4*)&Vr[3 * DD];
            o0 += p4.x * v0.x + p4.y * v1.x + p4.z * v2.x + p4.w * v3.x;
            o1 += p4.x * v0.y + p4.y * v1.y + p4.z * v2.y + p4.w * v3.y;
            o2 += p4.x * v0.z + p4.y * v1.z + p4.z * v2.z + p4.w * v3.z;
            o3 += p4.x * v0.w + p4.y * v1.w + p4.z * v2.w + p4.w * v3.w;
        }
    }

    // write O
    float* Orow = out + ((size_t)b * LQ + q0 + r2) * DD + dg * 4;
    *(float4*)Orow = make_float4(o0, o1, o2, o3);
}

extern "C" void kernel_launch(void* const* d_in, const int* in_sizes, int n_in,
                              void* d_out, int out_size)
{
    (void)in_sizes; (void)n_in; (void)out_size;
    const float* q = (const float*)d_in[0];
    const float* k = (const float*)d_in[1];
    const float* v = (const float*)d_in[2];
    const int*   mask = (const int*)d_in[3];

    float* outp = (float*)d_out;                       // [B, LQ, DD]  (tuple elem 0)
    float* attn = outp + (size_t)BATCH * LQ * DD;      // [B, LQ, LK]  (tuple elem 1)

    const int smem_bytes = SMEM_FLOATS * (int)sizeof(float);
    cudaFuncSetAttribute(sdpa_fused_kernel,
                         cudaFuncAttributeMaxDynamicSharedMemorySize, smem_bytes);

    dim3 grid(BATCH * (LQ / RQ));   // 64 * 64 = 4096 CTAs
    dim3 block(NTHR);
    sdpa_fused_kernel<<<grid, block, smem_bytes>>>(q, k, v, mask, outp, attn);
}

// round 6
// speedup vs baseline: 2.6005x; 2.6005x over previous
#include <cuda_runtime.h>
#include <cuda_bf16.h>
#include <cstdint>
#include <math.h>

#define DI __device__ __forceinline__

#define BATCH 64
#define L     1024
#define DDIM  64
#define BM    32
#define NTHR  256
#define SS    1032          // S row stride (floats)
#define SK    72            // Q/K/V row stride (halves)
#define SP    136           // P row stride (halves)

// smem byte offsets (all 16B aligned)
#define SM_S    0           // 32*1032*4      = 132096
#define SM_QHI  132096      // 32*72*2        = 4608
#define SM_QLO  136704
#define SM_KHI  141312      // 128*72*2       = 18432  (K, later V)
#define SM_KLO  159744
#define SM_PHI  178176      // 32*136*2       = 8704
#define SM_PLO  186880
#define SM_RED  195584      // float[32][4]
#define SM_M    196096      // float[32]
#define SM_IL   196224      // float[32]
#define SM_TOT  196352

DI uint32_t smem_u32(const void* p){ uint32_t a;
  asm("{ .reg .u64 t; cvta.to.shared.u64 t, %1; cvt.u32.u64 %0, t; }":"=r"(a):"l"(p)); return a; }

DI void split2(float x, float y, uint32_t& hi, uint32_t& lo){
  __nv_bfloat16 hx = __float2bfloat16_rn(x), hy = __float2bfloat16_rn(y);
  float rx = x - __bfloat162float(hx), ry = y - __bfloat162float(hy);
  __nv_bfloat162 H; H.x = hx; H.y = hy;
  __nv_bfloat162 L2 = __floats2bfloat162_rn(rx, ry);
  hi = *reinterpret_cast<uint32_t*>(&H);
  lo = *reinterpret_cast<uint32_t*>(&L2);
}

DI void ldmx4(uint32_t* r, uint32_t addr){
  asm volatile("ldmatrix.sync.aligned.m8n8.x4.shared.b16 {%0,%1,%2,%3}, [%4];"
    : "=r"(r[0]),"=r"(r[1]),"=r"(r[2]),"=r"(r[3]) : "r"(addr));
}
DI void ldmx4t(uint32_t* r, uint32_t addr){
  asm volatile("ldmatrix.sync.aligned.m8n8.x4.trans.shared.b16 {%0,%1,%2,%3}, [%4];"
    : "=r"(r[0]),"=r"(r[1]),"=r"(r[2]),"=r"(r[3]) : "r"(addr));
}
DI void mma16816(float* c, const uint32_t* a, uint32_t b0, uint32_t b1){
  asm volatile("mma.sync.aligned.m16n8k16.row.col.f32.bf16.bf16.f32 "
    "{%0,%1,%2,%3}, {%4,%5,%6,%7}, {%8,%9}, {%0,%1,%2,%3};"
    : "+f"(c[0]),"+f"(c[1]),"+f"(c[2]),"+f"(c[3])
    : "r"(a[0]),"r"(a[1]),"r"(a[2]),"r"(a[3]), "r"(b0),"r"(b1));
}

__global__ void __launch_bounds__(NTHR, 1)
sdpa_mma_kernel(const float* __restrict__ q, const float* __restrict__ k,
                const float* __restrict__ v, const int* __restrict__ mask,
                float* __restrict__ out, float* __restrict__ attn)
{
    extern __shared__ char sm[];
    const uint32_t smb = smem_u32(sm);
    float* S     = (float*)(sm + SM_S);
    float* RED   = (float*)(sm + SM_RED);
    float* Mrow  = (float*)(sm + SM_M);
    float* ILrow = (float*)(sm + SM_IL);

    const int tid  = threadIdx.x;
    const int wid  = tid >> 5, lane = tid & 31;
    const int wr   = wid >> 2, wc = wid & 3;
    const int g    = lane >> 3, l7 = lane & 7;
    const int b    = blockIdx.x >> 5;
    const int q0   = (blockIdx.x & 31) * BM;

    // ---- stage Q (pre-scaled 1/8) as bf16 hi/lo ----
    const float* Qg = q + ((size_t)(b * L + q0)) * DDIM;
    #pragma unroll
    for (int j = 0; j < 4; ++j) {
        int id = tid + j * NTHR;              // 1024 float2
        int r = id >> 5, c = (id & 31) * 2;
        float2 x = *(const float2*)&Qg[r * DDIM + c];
        uint32_t hi, lo; split2(x.x * 0.125f, x.y * 0.125f, hi, lo);
        *(uint32_t*)(sm + SM_QHI + r * (SK*2) + c*2) = hi;
        *(uint32_t*)(sm + SM_QLO + r * (SK*2) + c*2) = lo;
    }
    __syncthreads();

    // ---- preload Q A-fragments (kept in regs for whole GEMM1) ----
    uint32_t aH[4][4], aL[4][4];
    {
        int arow = l7 + (g & 1) * 8;
        int akoff = (g >> 1) * 8;
        #pragma unroll
        for (int ks = 0; ks < 4; ++ks) {
            uint32_t off = (uint32_t)((wr*16 + arow) * SK + ks*16 + akoff) * 2;
            ldmx4(aH[ks], smb + SM_QHI + off);
            ldmx4(aL[ks], smb + SM_QLO + off);
        }
    }

    float rmaxA = -INFINITY, rmaxB = -INFINITY;
    const float* Kg = k + (size_t)b * L * DDIM;
    const int rowA = wr * 16 + (lane >> 2);
    const int rowB = rowA + 8;

    // =========================== GEMM 1: S = (Q/8) K^T ===========================
    for (int kt = 0; kt < 8; ++kt) {
        __syncthreads();
        const float* Ks = Kg + (size_t)kt * 128 * DDIM;
        #pragma unroll
        for (int j = 0; j < 16; ++j) {
            int id = tid + j * NTHR;          // 4096 float2
            int r = id >> 5, c = (id & 31) * 2;
            float2 x = *(const float2*)&Ks[r * DDIM + c];
            uint32_t hi, lo; split2(x.x, x.y, hi, lo);
            *(uint32_t*)(sm + SM_KHI + r * (SK*2) + c*2) = hi;
            *(uint32_t*)(sm + SM_KLO + r * (SK*2) + c*2) = lo;
        }
        __syncthreads();

        float c4[4][4];
        #pragma unroll
        for (int i = 0; i < 4; ++i)
            #pragma unroll
            for (int jj = 0; jj < 4; ++jj) c4[i][jj] = 0.f;

        int brow = l7 + (g >> 1) * 8;
        int bkoff = (g & 1) * 8;
        #pragma unroll
        for (int ks = 0; ks < 4; ++ks) {
            #pragma unroll
            for (int ng = 0; ng < 2; ++ng) {
                uint32_t off = (uint32_t)((wc*32 + ng*16 + brow) * SK + ks*16 + bkoff) * 2;
                uint32_t bh[4], bl[4];
                ldmx4(bh, smb + SM_KHI + off);
                ldmx4(bl, smb + SM_KLO + off);
                mma16816(c4[2*ng],   aH[ks], bh[0], bh[1]);
                mma16816(c4[2*ng],   aL[ks], bh[0], bh[1]);
                mma16816(c4[2*ng],   aH[ks], bl[0], bl[1]);
                mma16816(c4[2*ng+1], aH[ks], bh[2], bh[3]);
                mma16816(c4[2*ng+1], aL[ks], bh[2], bh[3]);
                mma16816(c4[2*ng+1], aH[ks], bl[2], bl[3]);
            }
        }

        // epilogue: mask, store S, track row max
        #pragma unroll
        for (int nf = 0; nf < 4; ++nf) {
            int col = kt*128 + wc*32 + nf*8 + (lane & 3)*2;
            int2 ma = *(const int2*)&mask[((size_t)(b*L + q0 + rowA))*L + col];
            int2 mb = *(const int2*)&mask[((size_t)(b*L + q0 + rowB))*L + col];
            float s0 = ma.x ? -1e9f : c4[nf][0];
            float s1 = ma.y ? -1e9f : c4[nf][1];
            float s2 = mb.x ? -1e9f : c4[nf][2];
            float s3 = mb.y ? -1e9f : c4[nf][3];
            rmaxA = fmaxf(rmaxA, fmaxf(s0, s1));
            rmaxB = fmaxf(rmaxB, fmaxf(s2, s3));
            *(float2*)&S[rowA*SS + col] = make_float2(s0, s1);
            *(float2*)&S[rowB*SS + col] = make_float2(s2, s3);
        }
    }

    // ---- row max reduce ----
    rmaxA = fmaxf(rmaxA, __shfl_xor_sync(0xffffffffu, rmaxA, 1));
    rmaxA = fmaxf(rmaxA, __shfl_xor_sync(0xffffffffu, rmaxA, 2));
    rmaxB = fmaxf(rmaxB, __shfl_xor_sync(0xffffffffu, rmaxB, 1));
    rmaxB = fmaxf(rmaxB, __shfl_xor_sync(0xffffffffu, rmaxB, 2));
    if ((lane & 3) == 0) {
        RED[rowA*4 + wc] = rmaxA;
        RED[rowB*4 + wc] = rmaxB;
    }
    __syncthreads();
    if (tid < 32)
        Mrow[tid] = fmaxf(fmaxf(RED[tid*4], RED[tid*4+1]),
                          fmaxf(RED[tid*4+2], RED[tid*4+3]));
    __syncthreads();

    // ---- l pass: sum of exp ----
    {
        int r = tid >> 3, sub = tid & 7;
        float m = Mrow[r];
        float sum = 0.f;
        for (int c4i = sub; c4i < 256; c4i += 8) {
            float4 s4 = *(const float4*)&S[r*SS + c4i*4];
            sum += __expf(s4.x - m) + __expf(s4.y - m)
                 + __expf(s4.z - m) + __expf(s4.w - m);
        }
        sum += __shfl_xor_sync(0xffffffffu, sum, 1);
        sum += __shfl_xor_sync(0xffffffffu, sum, 2);
        sum += __shfl_xor_sync(0xffffffffu, sum, 4);
        if (sub == 0) ILrow[r] = 1.f / sum;
    }

    // =========================== GEMM 2: O = P V ===========================
    float o[2][4];
    #pragma unroll
    for (int i = 0; i < 2; ++i)
        #pragma unroll
        for (int jj = 0; jj < 4; ++jj) o[i][jj] = 0.f;

    const float* Vg = v + (size_t)b * L * DDIM;
    float* Ab = attn + ((size_t)(b * L + q0)) * L;

    for (int kt = 0; kt < 8; ++kt) {
        __syncthreads();   // prev-iter frag reads done; also publishes ILrow on kt=0
        // stage V tile [128 k x 64 d] hi/lo
        const float* Vs = Vg + (size_t)kt * 128 * DDIM;
        #pragma unroll
        for (int j = 0; j < 16; ++j) {
            int id = tid + j * NTHR;
            int r = id >> 5, c = (id & 31) * 2;
            float2 x = *(const float2*)&Vs[r * DDIM + c];
            uint32_t hi, lo; split2(x.x, x.y, hi, lo);
            *(uint32_t*)(sm + SM_KHI + r * (SK*2) + c*2) = hi;
            *(uint32_t*)(sm + SM_KLO + r * (SK*2) + c*2) = lo;
        }
        // stage P tile: p = exp(s-m)*il, write attn + hi/lo smem
        #pragma unroll
        for (int j = 0; j < 4; ++j) {
            int id = tid + j * NTHR;          // 1024 float4 over 32x128
            int r = id >> 5, cc = (id & 31) * 4;
            float m = Mrow[r], il = ILrow[r];
            float4 s4 = *(const float4*)&S[r*SS + kt*128 + cc];
            float p0 = __expf(s4.x - m) * il;
            float p1 = __expf(s4.y - m) * il;
            float p2 = __expf(s4.z - m) * il;
            float p3 = __expf(s4.w - m) * il;
            *(float4*)&Ab[(size_t)r * L + kt*128 + cc] = make_float4(p0, p1, p2, p3);
            uint32_t h0, l0, h1, l1;
            split2(p0, p1, h0, l0);
            split2(p2, p3, h1, l1);
            *(uint2*)(sm + SM_PHI + r * (SP*2) + cc*2) = make_uint2(h0, h1);
            *(uint2*)(sm + SM_PLO + r * (SP*2) + cc*2) = make_uint2(l0, l1);
        }
        __syncthreads();

        int arow = l7 + (g & 1) * 8, akoff = (g >> 1) * 8;
        int vrow = l7 + (g & 1) * 8, vnoff = (g >> 1) * 8;
        #pragma unroll
        for (int ks = 0; ks < 8; ++ks) {
            uint32_t pH[4], pL[4], vh[4], vl[4];
            uint32_t aoff = (uint32_t)((wr*16 + arow) * SP + ks*16 + akoff) * 2;
            ldmx4(pH, smb + SM_PHI + aoff);
            ldmx4(pL, smb + SM_PLO + aoff);
            uint32_t boff = (uint32_t)((ks*16 + vrow) * SK + wc*16 + vnoff) * 2;
            ldmx4t(vh, smb + SM_KHI + boff);
            ldmx4t(vl, smb + SM_KLO + boff);
            mma16816(o[0], pH, vh[0], vh[1]);
            mma16816(o[0], pL, vh[0], vh[1]);
            mma16816(o[0], pH, vl[0], vl[1]);
            mma16816(o[1], pH, vh[2], vh[3]);
            mma16816(o[1], pL, vh[2], vh[3]);
            mma16816(o[1], pH, vl[2], vl[3]);
        }
    }

    // ---- write O ----
    #pragma unroll
    for (int f = 0; f < 2; ++f) {
        int col = wc*16 + f*8 + (lane & 3)*2;
        *(float2*)&out[((size_t)(b*L + q0 + rowA))*DDIM + col] = make_float2(o[f][0], o[f][1]);
        *(float2*)&out[((size_t)(b*L + q0 + rowB))*DDIM + col] = make_float2(o[f][2], o[f][3]);
    }
}

extern "C" void kernel_launch(void* const* d_in, const int* in_sizes, int n_in,
                              void* d_out, int out_size)
{
    (void)in_sizes; (void)n_in; (void)out_size;
    const float* q = (const float*)d_in[0];
    const float* k = (const float*)d_in[1];
    const float* v = (const float*)d_in[2];
    const int*   mask = (const int*)d_in[3];

    float* outp = (float*)d_out;                            // [B, LQ, DD]
    float* attn = outp + (size_t)BATCH * L * DDIM;          // [B, LQ, LK]

    cudaFuncSetAttribute(sdpa_mma_kernel,
                         cudaFuncAttributeMaxDynamicSharedMemorySize, SM_TOT);

    dim3 grid(BATCH * (L / BM));    // 2048
    sdpa_mma_kernel<<<grid, NTHR, SM_TOT>>>(q, k, v, mask, outp, attn);
}

// round 8
// speedup vs baseline: 3.0435x; 1.1704x over previous
#include <cuda_runtime.h>
#include <cuda_bf16.h>
#include <cstdint>
#include <math.h>

#define DI __device__ __forceinline__

#define BATCH 64
#define L     1024
#define DDIM  64
#define BM    32
#define NTHR  512
#define SS    1032          // S row stride (floats)
#define SK    72            // Q/K/V row stride (halves)
#define SP    136           // P row stride (halves)

// smem byte offsets (16B aligned)
#define SM_S    0           // 32*1032*4 = 132096
#define SM_QHI  132096      // 32*72*2   = 4608
#define SM_QLO  136704
#define SM_KHI  141312      // 128*72*2  = 18432  (K, later V)
#define SM_KLO  159744
#define SM_PHI  178176      // 32*136*2  = 8704
#define SM_PLO  186880
#define SM_RED  195584      // float[32][8] = 1024
#define SM_M    196608      // float[32]
#define SM_IL   196736      // float[32]
#define SM_TOT  196864

DI uint32_t smem_u32(const void* p){ uint32_t a;
  asm("{ .reg .u64 t; cvta.to.shared.u64 t, %1; cvt.u32.u64 %0, t; }":"=r"(a):"l"(p)); return a; }

DI void split2(float x, float y, uint32_t& hi, uint32_t& lo){
  __nv_bfloat16 hx = __float2bfloat16_rn(x), hy = __float2bfloat16_rn(y);
  float rx = x - __bfloat162float(hx), ry = y - __bfloat162float(hy);
  __nv_bfloat162 H; H.x = hx; H.y = hy;
  __nv_bfloat162 L2 = __floats2bfloat162_rn(rx, ry);
  hi = *reinterpret_cast<uint32_t*>(&H);
  lo = *reinterpret_cast<uint32_t*>(&L2);
}

DI void ldmx4(uint32_t* r, uint32_t addr){
  asm volatile("ldmatrix.sync.aligned.m8n8.x4.shared.b16 {%0,%1,%2,%3}, [%4];"
    : "=r"(r[0]),"=r"(r[1]),"=r"(r[2]),"=r"(r[3]) : "r"(addr));
}
DI void ldmx2t(uint32_t* r, uint32_t addr){
  asm volatile("ldmatrix.sync.aligned.m8n8.x2.trans.shared.b16 {%0,%1}, [%2];"
    : "=r"(r[0]),"=r"(r[1]) : "r"(addr));
}
DI void mma16816(float* c, const uint32_t* a, uint32_t b0, uint32_t b1){
  asm volatile("mma.sync.aligned.m16n8k16.row.col.f32.bf16.bf16.f32 "
    "{%0,%1,%2,%3}, {%4,%5,%6,%7}, {%8,%9}, {%0,%1,%2,%3};"
    : "+f"(c[0]),"+f"(c[1]),"+f"(c[2]),"+f"(c[3])
    : "r"(a[0]),"r"(a[1]),"r"(a[2]),"r"(a[3]), "r"(b0),"r"(b1));
}

__global__ void __launch_bounds__(NTHR, 1)
sdpa_mma_kernel(const float* __restrict__ q, const float* __restrict__ k,
                const float* __restrict__ v, const int* __restrict__ mask,
                float* __restrict__ out, float* __restrict__ attn)
{
    extern __shared__ char sm[];
    const uint32_t smb = smem_u32(sm);
    float* S     = (float*)(sm + SM_S);
    float* RED   = (float*)(sm + SM_RED);
    float* Mrow  = (float*)(sm + SM_M);
    float* ILrow = (float*)(sm + SM_IL);

    const int tid  = threadIdx.x;
    const int wid  = tid >> 5, lane = tid & 31;
    const int wr   = wid >> 3, wc = wid & 7;    // 2 x 8 warp grid
    const int g    = lane >> 3, l7 = lane & 7;
    const int b    = blockIdx.x >> 5;
    const int q0   = (blockIdx.x & 31) * BM;

    // ---- stage Q (pre-scaled 1/8) as bf16 hi/lo ----
    const float* Qg = q + ((size_t)(b * L + q0)) * DDIM;
    #pragma unroll
    for (int j = 0; j < 2; ++j) {
        int id = tid + j * NTHR;              // 1024 float2
        int r = id >> 5, c = (id & 31) * 2;
        float2 x = *(const float2*)&Qg[r * DDIM + c];
        uint32_t hi, lo; split2(x.x * 0.125f, x.y * 0.125f, hi, lo);
        *(uint32_t*)(sm + SM_QHI + r * (SK*2) + c*2) = hi;
        *(uint32_t*)(sm + SM_QLO + r * (SK*2) + c*2) = lo;
    }
    __syncthreads();

    // ---- preload Q A-fragments (regs for whole GEMM1) ----
    uint32_t aH[4][4], aL[4][4];
    {
        int arow = wr*16 + l7 + (g & 1) * 8;
        int akoff = (g >> 1) * 8;
        #pragma unroll
        for (int ks = 0; ks < 4; ++ks) {
            uint32_t off = (uint32_t)(arow * SK + ks*16 + akoff) * 2;
            ldmx4(aH[ks], smb + SM_QHI + off);
            ldmx4(aL[ks], smb + SM_QLO + off);
        }
    }

    float rmaxA = -INFINITY, rmaxB = -INFINITY;
    const float* Kg = k + (size_t)b * L * DDIM;
    const int rowA = wr * 16 + (lane >> 2);
    const int rowB = rowA + 8;

    const int str = tid >> 5;             // staging row base
    const int stc = (tid & 31) * 2;       // staging col

    // prefetch K tile 0
    float2 kreg[8];
    #pragma unroll
    for (int j = 0; j < 8; ++j)
        kreg[j] = *(const float2*)&Kg[(size_t)(str + j*16) * DDIM + stc];

    // =========================== GEMM 1: S = (Q/8) K^T ===========================
    for (int kt = 0; kt < 8; ++kt) {
        __syncthreads();                  // prev-tile frag reads done
        #pragma unroll
        for (int j = 0; j < 8; ++j) {
            uint32_t hi, lo; split2(kreg[j].x, kreg[j].y, hi, lo);
            *(uint32_t*)(sm + SM_KHI + (str + j*16) * (SK*2) + stc*2) = hi;
            *(uint32_t*)(sm + SM_KLO + (str + j*16) * (SK*2) + stc*2) = lo;
        }
        __syncthreads();
        if (kt < 7) {
            const float* Kn = Kg + (size_t)(kt + 1) * 128 * DDIM;
            #pragma unroll
            for (int j = 0; j < 8; ++j)
                kreg[j] = *(const float2*)&Kn[(size_t)(str + j*16) * DDIM + stc];
        }

        float c4[2][4];
        #pragma unroll
        for (int i = 0; i < 2; ++i)
            #pragma unroll
            for (int jj = 0; jj < 4; ++jj) c4[i][jj] = 0.f;

        int brow = wc*16 + l7 + (g >> 1) * 8;
        int bkoff = (g & 1) * 8;
        #pragma unroll
        for (int ks = 0; ks < 4; ++ks) {
            uint32_t off = (uint32_t)(brow * SK + ks*16 + bkoff) * 2;
            uint32_t bh[4], bl[4];
            ldmx4(bh, smb + SM_KHI + off);
            ldmx4(bl, smb + SM_KLO + off);
            mma16816(c4[0], aH[ks], bh[0], bh[1]);
            mma16816(c4[0], aL[ks], bh[0], bh[1]);
            mma16816(c4[0], aH[ks], bl[0], bl[1]);
            mma16816(c4[1], aH[ks], bh[2], bh[3]);
            mma16816(c4[1], aL[ks], bh[2], bh[3]);
            mma16816(c4[1], aH[ks], bl[2], bl[3]);
        }

        // epilogue: mask, store S, track row max
        #pragma unroll
        for (int nf = 0; nf < 2; ++nf) {
            int col = kt*128 + wc*16 + nf*8 + (lane & 3)*2;
            int2 ma = *(const int2*)&mask[((size_t)(b*L + q0 + rowA))*L + col];
            int2 mb = *(const int2*)&mask[((size_t)(b*L + q0 + rowB))*L + col];
            float s0 = ma.x ? -1e9f : c4[nf][0];
            float s1 = ma.y ? -1e9f : c4[nf][1];
            float s2 = mb.x ? -1e9f : c4[nf][2];
            float s3 = mb.y ? -1e9f : c4[nf][3];
            rmaxA = fmaxf(rmaxA, fmaxf(s0, s1));
            rmaxB = fmaxf(rmaxB, fmaxf(s2, s3));
            *(float2*)&S[rowA*SS + col] = make_float2(s0, s1);
            *(float2*)&S[rowB*SS + col] = make_float2(s2, s3);
        }
    }

    // ---- row max reduce ----
    rmaxA = fmaxf(rmaxA, __shfl_xor_sync(0xffffffffu, rmaxA, 1));
    rmaxA = fmaxf(rmaxA, __shfl_xor_sync(0xffffffffu, rmaxA, 2));
    rmaxB = fmaxf(rmaxB, __shfl_xor_sync(0xffffffffu, rmaxB, 1));
    rmaxB = fmaxf(rmaxB, __shfl_xor_sync(0xffffffffu, rmaxB, 2));
    if ((lane & 3) == 0) {
        RED[rowA*8 + wc] = rmaxA;
        RED[rowB*8 + wc] = rmaxB;
    }
    __syncthreads();
    if (tid < 32) {
        float m = RED[tid*8];
        #pragma unroll
        for (int j = 1; j < 8; ++j) m = fmaxf(m, RED[tid*8 + j]);
        Mrow[tid] = m;
    }
    __syncthreads();

    // ---- l pass: sum of exp ----
    {
        int r = tid >> 4, sub = tid & 15;   // 32 rows x 16 threads
        float m = Mrow[r];
        float sum = 0.f;
        for (int c4i = sub; c4i < 256; c4i += 16) {
            float4 s4 = *(const float4*)&S[r*SS + c4i*4];
            sum += __expf(s4.x - m) + __expf(s4.y - m)
                 + __expf(s4.z - m) + __expf(s4.w - m);
        }
        sum += __shfl_xor_sync(0xffffffffu, sum, 1);
        sum += __shfl_xor_sync(0xffffffffu, sum, 2);
        sum += __shfl_xor_sync(0xffffffffu, sum, 4);
        sum += __shfl_xor_sync(0xffffffffu, sum, 8);
        if (sub == 0) ILrow[r] = 1.f / sum;
    }

    // =========================== GEMM 2: O = P V ===========================
    float o[4] = {0.f, 0.f, 0.f, 0.f};     // 16x8 warp tile

    const float* Vg = v + (size_t)b * L * DDIM;
    float* Ab = attn + ((size_t)(b * L + q0)) * L;

    // prefetch V tile 0
    #pragma unroll
    for (int j = 0; j < 8; ++j)
        kreg[j] = *(const float2*)&Vg[(size_t)(str + j*16) * DDIM + stc];

    for (int kt = 0; kt < 8; ++kt) {
        __syncthreads();   // prev-iter frag reads done; publishes ILrow on kt=0
        #pragma unroll
        for (int j = 0; j < 8; ++j) {
            uint32_t hi, lo; split2(kreg[j].x, kreg[j].y, hi, lo);
            *(uint32_t*)(sm + SM_KHI + (str + j*16) * (SK*2) + stc*2) = hi;
            *(uint32_t*)(sm + SM_KLO + (str + j*16) * (SK*2) + stc*2) = lo;
        }
        // stage P tile: p = exp(s-m)*il, write attn + hi/lo smem
        #pragma unroll
        for (int j = 0; j < 2; ++j) {
            int id = tid + j * NTHR;          // 1024 float4 over 32x128
            int r = id >> 5, cc = (id & 31) * 4;
            float m = Mrow[r], il = ILrow[r];
            float4 s4 = *(const float4*)&S[r*SS + kt*128 + cc];
            float p0 = __expf(s4.x - m) * il;
            float p1 = __expf(s4.y - m) * il;
            float p2 = __expf(s4.z - m) * il;
            float p3 = __expf(s4.w - m) * il;
            *(float4*)&Ab[(size_t)r * L + kt*128 + cc] = make_float4(p0, p1, p2, p3);
            uint32_t h0, l0, h1, l1;
            split2(p0, p1, h0, l0);
            split2(p2, p3, h1, l1);
            *(uint2*)(sm + SM_PHI + r * (SP*2) + cc*2) = make_uint2(h0, h1);
            *(uint2*)(sm + SM_PLO + r * (SP*2) + cc*2) = make_uint2(l0, l1);
        }
        __syncthreads();
        if (kt < 7) {
            const float* Vn = Vg + (size_t)(kt + 1) * 128 * DDIM;
            #pragma unroll
            for (int j = 0; j < 8; ++j)
                kreg[j] = *(const float2*)&Vn[(size_t)(str + j*16) * DDIM + stc];
        }

        int arow = wr*16 + l7 + (g & 1) * 8, akoff = (g >> 1) * 8;
        int vrow = lane & 15;
        #pragma unroll
        for (int ks = 0; ks < 8; ++ks) {
            uint32_t pH[4], pL[4], vh[2], vl[2];
            uint32_t aoff = (uint32_t)(arow * SP + ks*16 + akoff) * 2;
            ldmx4(pH, smb + SM_PHI + aoff);
            ldmx4(pL, smb + SM_PLO + aoff);
            uint32_t boff = (uint32_t)((ks*16 + vrow) * SK + wc*8) * 2;
            ldmx2t(vh, smb + SM_KHI + boff);
            ldmx2t(vl, smb + SM_KLO + boff);
            mma16816(o, pH, vh[0], vh[1]);
            mma16816(o, pL, vh[0], vh[1]);
            mma16816(o, pH, vl[0], vl[1]);
        }
    }

    // ---- write O ----
    {
        int col = wc*8 + (lane & 3)*2;
        *(float2*)&out[((size_t)(b*L + q0 + rowA))*DDIM + col] = make_float2(o[0], o[1]);
        *(float2*)&out[((size_t)(b*L + q0 + rowB))*DDIM + col] = make_float2(o[2], o[3]);
    }
}

extern "C" void kernel_launch(void* const* d_in, const int* in_sizes, int n_in,
                              void* d_out, int out_size)
{
    (void)in_sizes; (void)n_in; (void)out_size;
    const float* q = (const float*)d_in[0];
    const float* k = (const float*)d_in[1];
    const float* v = (const float*)d_in[2];
    const int*   mask = (const int*)d_in[3];

    float* outp = (float*)d_out;                            // [B, LQ, DD]
    float* attn = outp + (size_t)BATCH * L * DDIM;          // [B, LQ, LK]

    cudaFuncSetAttribute(sdpa_mma_kernel,
                         cudaFuncAttributeMaxDynamicSharedMemorySize, SM_TOT);

    dim3 grid(BATCH * (L / BM));    // 2048
    sdpa_mma_kernel<<<grid, NTHR, SM_TOT>>>(q, k, v, mask, outp, attn);
}

// round 12
// speedup vs baseline: 3.1193x; 1.0249x over previous
#include <cuda_runtime.h>
#include <cuda_bf16.h>
#include <cstdint>
#include <math.h>

#define DI __device__ __forceinline__

#define BATCH 64
#define L     1024
#define DDIM  64
#define BM    32
#define NTHR  512
#define SS    1032          // S row stride (floats)
#define SK    72            // Q/K/V row stride (halves)
#define SP    136           // P row stride (halves)

// smem byte offsets (16B aligned)  — identical layout to the passing R8 kernel
#define SM_S    0           // 32*1032*4 = 132096   (holds e = exp(masked s))
#define SM_QHI  132096      // 32*72*2   = 4608
#define SM_QLO  136704
#define SM_KHI  141312      // 128*72*2  = 18432  (K, later V)
#define SM_KLO  159744
#define SM_PHI  178176      // 32*136*2  = 8704
#define SM_PLO  186880
#define SM_RED  195584      // float[32][8] = 1024
#define SM_IL   196736      // float[32]
#define SM_TOT  196864

DI uint32_t smem_u32(const void* p){ uint32_t a;
  asm("{ .reg .u64 t; cvta.to.shared.u64 t, %1; cvt.u32.u64 %0, t; }":"=r"(a):"l"(p)); return a; }

DI void split2(float x, float y, uint32_t& hi, uint32_t& lo){
  __nv_bfloat16 hx = __float2bfloat16_rn(x), hy = __float2bfloat16_rn(y);
  float rx = x - __bfloat162float(hx), ry = y - __bfloat162float(hy);
  __nv_bfloat162 H; H.x = hx; H.y = hy;
  __nv_bfloat162 L2 = __floats2bfloat162_rn(rx, ry);
  hi = *reinterpret_cast<uint32_t*>(&H);
  lo = *reinterpret_cast<uint32_t*>(&L2);
}

DI void ldmx4(uint32_t* r, uint32_t addr){
  asm volatile("ldmatrix.sync.aligned.m8n8.x4.shared.b16 {%0,%1,%2,%3}, [%4];"
    : "=r"(r[0]),"=r"(r[1]),"=r"(r[2]),"=r"(r[3]) : "r"(addr));
}
DI void ldmx2t(uint32_t* r, uint32_t addr){
  asm volatile("ldmatrix.sync.aligned.m8n8.x2.trans.shared.b16 {%0,%1}, [%2];"
    : "=r"(r[0]),"=r"(r[1]) : "r"(addr));
}
DI void mma16816(float* c, const uint32_t* a, uint32_t b0, uint32_t b1){
  asm volatile("mma.sync.aligned.m16n8k16.row.col.f32.bf16.bf16.f32 "
    "{%0,%1,%2,%3}, {%4,%5,%6,%7}, {%8,%9}, {%0,%1,%2,%3};"
    : "+f"(c[0]),"+f"(c[1]),"+f"(c[2]),"+f"(c[3])
    : "r"(a[0]),"r"(a[1]),"r"(a[2]),"r"(a[3]), "r"(b0),"r"(b1));
}

__global__ void __launch_bounds__(NTHR, 1)
sdpa_mma_kernel(const float* __restrict__ q, const float* __restrict__ k,
                const float* __restrict__ v, const int* __restrict__ mask,
                float* __restrict__ out, float* __restrict__ attn)
{
    extern __shared__ char sm[];
    const uint32_t smb = smem_u32(sm);
    float* S     = (float*)(sm + SM_S);
    float* RED   = (float*)(sm + SM_RED);
    float* ILrow = (float*)(sm + SM_IL);

    const int tid  = threadIdx.x;
    const int wid  = tid >> 5, lane = tid & 31;
    const int wr   = wid >> 3, wc = wid & 7;    // 2 x 8 warp grid
    const int g    = lane >> 3, l7 = lane & 7;
    const int b    = blockIdx.x >> 5;
    const int q0   = (blockIdx.x & 31) * BM;

    // ---- stage Q (pre-scaled 1/8) as bf16 hi/lo ----
    const float* Qg = q + ((size_t)(b * L + q0)) * DDIM;
    #pragma unroll
    for (int j = 0; j < 2; ++j) {
        int id = tid + j * NTHR;              // 1024 float2
        int r = id >> 5, c = (id & 31) * 2;
        float2 x = *(const float2*)&Qg[r * DDIM + c];
        uint32_t hi, lo; split2(x.x * 0.125f, x.y * 0.125f, hi, lo);
        *(uint32_t*)(sm + SM_QHI + r * (SK*2) + c*2) = hi;
        *(uint32_t*)(sm + SM_QLO + r * (SK*2) + c*2) = lo;
    }
    __syncthreads();

    // ---- preload Q A-fragments (regs for whole GEMM1) ----
    uint32_t aH[4][4], aL[4][4];
    {
        int arow = wr*16 + l7 + (g & 1) * 8;
        int akoff = (g >> 1) * 8;
        #pragma unroll
        for (int ks = 0; ks < 4; ++ks) {
            uint32_t off = (uint32_t)(arow * SK + ks*16 + akoff) * 2;
            ldmx4(aH[ks], smb + SM_QHI + off);
            ldmx4(aL[ks], smb + SM_QLO + off);
        }
    }

    float lsumA = 0.f, lsumB = 0.f;
    const float* Kg = k + (size_t)b * L * DDIM;
    const int rowA = wr * 16 + (lane >> 2);
    const int rowB = rowA + 8;
    const size_t grA = (size_t)(b*L + q0 + rowA) * L;
    const size_t grB = (size_t)(b*L + q0 + rowB) * L;

    const int str = tid >> 5;             // staging row base
    const int stc = (tid & 31) * 2;       // staging col

    // prefetch K tile 0
    float2 kreg[8];
    #pragma unroll
    for (int j = 0; j < 8; ++j)
        kreg[j] = *(const float2*)&Kg[(size_t)(str + j*16) * DDIM + stc];

    // =================== GEMM 1: e = exp(mask(Q K^T / 8)), l accumulated ===================
    for (int kt = 0; kt < 8; ++kt) {
        __syncthreads();                  // prev-tile frag reads done
        #pragma unroll
        for (int j = 0; j < 8; ++j) {
            uint32_t hi, lo; split2(kreg[j].x, kreg[j].y, hi, lo);
            *(uint32_t*)(sm + SM_KHI + (str + j*16) * (SK*2) + stc*2) = hi;
            *(uint32_t*)(sm + SM_KLO + (str + j*16) * (SK*2) + stc*2) = lo;
        }
        __syncthreads();
        if (kt < 7) {
            const float* Kn = Kg + (size_t)(kt + 1) * 128 * DDIM;
            #pragma unroll
            for (int j = 0; j < 8; ++j)
                kreg[j] = *(const float2*)&Kn[(size_t)(str + j*16) * DDIM + stc];
        }

        // hoist mask loads for THIS tile: latency hides behind the MMA phase
        int2 cmA[2], cmB[2];
        #pragma unroll
        for (int nf = 0; nf < 2; ++nf) {
            int col = kt*128 + wc*16 + nf*8 + (lane & 3)*2;
            cmA[nf] = *(const int2*)&mask[grA + col];
            cmB[nf] = *(const int2*)&mask[grB + col];
        }

        float c4[2][4];
        #pragma unroll
        for (int i = 0; i < 2; ++i)
            #pragma unroll
            for (int jj = 0; jj < 4; ++jj) c4[i][jj] = 0.f;

        int brow = wc*16 + l7 + (g >> 1) * 8;
        int bkoff = (g & 1) * 8;
        #pragma unroll
        for (int ks = 0; ks < 4; ++ks) {
            uint32_t off = (uint32_t)(brow * SK + ks*16 + bkoff) * 2;
            uint32_t bh[4], bl[4];
            ldmx4(bh, smb + SM_KHI + off);
            ldmx4(bl, smb + SM_KLO + off);
            mma16816(c4[0], aH[ks], bh[0], bh[1]);
            mma16816(c4[0], aL[ks], bh[0], bh[1]);
            mma16816(c4[0], aH[ks], bl[0], bl[1]);
            mma16816(c4[1], aH[ks], bh[2], bh[3]);
            mma16816(c4[1], aL[ks], bh[2], bh[3]);
            mma16816(c4[1], aH[ks], bl[2], bl[3]);
        }

        // epilogue: mask -> e = exp(s) (0 if masked), accumulate l, store e
        #pragma unroll
        for (int nf = 0; nf < 2; ++nf) {
            int col = kt*128 + wc*16 + nf*8 + (lane & 3)*2;
            float e0 = cmA[nf].x ? 0.f : __expf(c4[nf][0]);
            float e1 = cmA[nf].y ? 0.f : __expf(c4[nf][1]);
            float e2 = cmB[nf].x ? 0.f : __expf(c4[nf][2]);
            float e3 = cmB[nf].y ? 0.f : __expf(c4[nf][3]);
            lsumA += e0 + e1;
            lsumB += e2 + e3;
            *(float2*)&S[rowA*SS + col] = make_float2(e0, e1);
            *(float2*)&S[rowB*SS + col] = make_float2(e2, e3);
        }
    }

    // ---- row-sum reduce (quad shuffles + 32x8 merge) ----
    lsumA += __shfl_xor_sync(0xffffffffu, lsumA, 1);
    lsumA += __shfl_xor_sync(0xffffffffu, lsumA, 2);
    lsumB += __shfl_xor_sync(0xffffffffu, lsumB, 1);
    lsumB += __shfl_xor_sync(0xffffffffu, lsumB, 2);
    if ((lane & 3) == 0) {
        RED[rowA*8 + wc] = lsumA;
        RED[rowB*8 + wc] = lsumB;
    }
    __syncthreads();
    if (tid < 32) {
        float s8 = RED[tid*8];
        #pragma unroll
        for (int j = 1; j < 8; ++j) s8 += RED[tid*8 + j];
        ILrow[tid] = 1.f / s8;
    }
    __syncthreads();

    // =========================== GEMM 2: O = P V ===========================
    float o[4] = {0.f, 0.f, 0.f, 0.f};     // 16x8 warp tile

    const float* Vg = v + (size_t)b * L * DDIM;
    float* Ab = attn + ((size_t)(b * L + q0)) * L;

    // prefetch V tile 0
    #pragma unroll
    for (int j = 0; j < 8; ++j)
        kreg[j] = *(const float2*)&Vg[(size_t)(str + j*16) * DDIM + stc];

    for (int kt = 0; kt < 8; ++kt) {
        __syncthreads();   // prev-iter frag reads done
        #pragma unroll
        for (int j = 0; j < 8; ++j) {
            uint32_t hi, lo; split2(kreg[j].x, kreg[j].y, hi, lo);
            *(uint32_t*)(sm + SM_KHI + (str + j*16) * (SK*2) + stc*2) = hi;
            *(uint32_t*)(sm + SM_KLO + (str + j*16) * (SK*2) + stc*2) = lo;
        }
        // stage P tile: p = e * il (no exp here), write attn + hi/lo smem
        #pragma unroll
        for (int j = 0; j < 2; ++j) {
            int id = tid + j * NTHR;          // 1024 float4 over 32x128
            int r = id >> 5, cc = (id & 31) * 4;
            float il = ILrow[r];
            float4 e4 = *(const float4*)&S[r*SS + kt*128 + cc];
            float p0 = e4.x * il, p1 = e4.y * il, p2 = e4.z * il, p3 = e4.w * il;
            *(float4*)&Ab[(size_t)r * L + kt*128 + cc] = make_float4(p0, p1, p2, p3);
            uint32_t h0, l0, h1, l1;
            split2(p0, p1, h0, l0);
            split2(p2, p3, h1, l1);
            *(uint2*)(sm + SM_PHI + r * (SP*2) + cc*2) = make_uint2(h0, h1);
            *(uint2*)(sm + SM_PLO + r * (SP*2) + cc*2) = make_uint2(l0, l1);
        }
        __syncthreads();
        if (kt < 7) {
            const float* Vn = Vg + (size_t)(kt + 1) * 128 * DDIM;
            #pragma unroll
            for (int j = 0; j < 8; ++j)
                kreg[j] = *(const float2*)&Vn[(size_t)(str + j*16) * DDIM + stc];
        }

        int arow = wr*16 + l7 + (g & 1) * 8, akoff = (g >> 1) * 8;
        int vrow = lane & 15;
        #pragma unroll
        for (int ks = 0; ks < 8; ++ks) {
            uint32_t pH[4], pL[4], vh[2], vl[2];
            uint32_t aoff = (uint32_t)(arow * SP + ks*16 + akoff) * 2;
            ldmx4(pH, smb + SM_PHI + aoff);
            ldmx4(pL, smb + SM_PLO + aoff);
            uint32_t boff = (uint32_t)((ks*16 + vrow) * SK + wc*8) * 2;
            ldmx2t(vh, smb + SM_KHI + boff);
            ldmx2t(vl, smb + SM_KLO + boff);
            mma16816(o, pH, vh[0], vh[1]);
            mma16816(o, pL, vh[0], vh[1]);
            mma16816(o, pH, vl[0], vl[1]);
        }
    }

    // ---- write O ----
    {
        int col = wc*8 + (lane & 3)*2;
        *(float2*)&out[((size_t)(b*L + q0 + rowA))*DDIM + col] = make_float2(o[0], o[1]);
        *(float2*)&out[((size_t)(b*L + q0 + rowB))*DDIM + col] = make_float2(o[2], o[3]);
    }
}

extern "C" void kernel_launch(void* const* d_in, const int* in_sizes, int n_in,
                              void* d_out, int out_size)
{
    (void)in_sizes; (void)n_in; (void)out_size;
    const float* q = (const float*)d_in[0];
    const float* k = (const float*)d_in[1];
    const float* v = (const float*)d_in[2];
    const int*   mask = (const int*)d_in[3];

    float* outp = (float*)d_out;                            // [B, LQ, DD]
    float* attn = outp + (size_t)BATCH * L * DDIM;          // [B, LQ, LK]

    cudaFuncSetAttribute(sdpa_mma_kernel,
                         cudaFuncAttributeMaxDynamicSharedMemorySize, SM_TOT);

    dim3 grid(BATCH * (L / BM));    // 2048
    sdpa_mma_kernel<<<grid, NTHR, SM_TOT>>>(q, k, v, mask, outp, attn);
}

// round 13
// speedup vs baseline: 3.1700x; 1.0163x over previous
#include <cuda_runtime.h>
#include <cuda_bf16.h>
#include <cstdint>
#include <math.h>

#define DI __device__ __forceinline__

#define BATCH 64
#define L     1024
#define DDIM  64
#define BM    32
#define NTHR  256
#define SK    72            // smem row stride (halves) for Q/K/V/P

// smem byte offsets (16B aligned) — total 37504 B => 2 CTAs/SM
#define SM_QHI  0           // 32*144 = 4608
#define SM_QLO  4608
#define SM_KHI  9216        // 64*144 = 9216  (K, later V)
#define SM_KLO  18432
#define SM_PHI  27648       // 32*144 = 4608
#define SM_PLO  32256
#define SM_RED  36864       // float[32][4] = 512
#define SM_IL   37376       // float[32]
#define SM_TOT  37504

DI uint32_t smem_u32(const void* p){ uint32_t a;
  asm("{ .reg .u64 t; cvta.to.shared.u64 t, %1; cvt.u32.u64 %0, t; }":"=r"(a):"l"(p)); return a; }

DI void split2(float x, float y, uint32_t& hi, uint32_t& lo){
  __nv_bfloat16 hx = __float2bfloat16_rn(x), hy = __float2bfloat16_rn(y);
  float rx = x - __bfloat162float(hx), ry = y - __bfloat162float(hy);
  __nv_bfloat162 H; H.x = hx; H.y = hy;
  __nv_bfloat162 L2 = __floats2bfloat162_rn(rx, ry);
  hi = *reinterpret_cast<uint32_t*>(&H);
  lo = *reinterpret_cast<uint32_t*>(&L2);
}

DI void ldmx4(uint32_t* r, uint32_t addr){
  asm volatile("ldmatrix.sync.aligned.m8n8.x4.shared.b16 {%0,%1,%2,%3}, [%4];"
    : "=r"(r[0]),"=r"(r[1]),"=r"(r[2]),"=r"(r[3]) : "r"(addr));
}
DI void ldmx4t(uint32_t* r, uint32_t addr){
  asm volatile("ldmatrix.sync.aligned.m8n8.x4.trans.shared.b16 {%0,%1,%2,%3}, [%4];"
    : "=r"(r[0]),"=r"(r[1]),"=r"(r[2]),"=r"(r[3]) : "r"(addr));
}
DI void mma16816(float* c, const uint32_t* a, uint32_t b0, uint32_t b1){
  asm volatile("mma.sync.aligned.m16n8k16.row.col.f32.bf16.bf16.f32 "
    "{%0,%1,%2,%3}, {%4,%5,%6,%7}, {%8,%9}, {%0,%1,%2,%3};"
    : "+f"(c[0]),"+f"(c[1]),"+f"(c[2]),"+f"(c[3])
    : "r"(a[0]),"r"(a[1]),"r"(a[2]),"r"(a[3]), "r"(b0),"r"(b1));
}

__global__ void __launch_bounds__(NTHR, 2)
sdpa_mma_kernel(const float* __restrict__ q, const float* __restrict__ k,
                const float* __restrict__ v, const int* __restrict__ mask,
                float* __restrict__ out, float* __restrict__ attn)
{
    extern __shared__ char sm[];
    const uint32_t smb = smem_u32(sm);
    float* RED   = (float*)(sm + SM_RED);
    float* ILrow = (float*)(sm + SM_IL);

    const int tid  = threadIdx.x;
    const int wid  = tid >> 5, lane = tid & 31;
    const int wr   = wid >> 2, wc = wid & 3;    // 2 x 4 warp grid
    const int g    = lane >> 3, l7 = lane & 7;
    const int b    = blockIdx.x >> 5;
    const int q0   = (blockIdx.x & 31) * BM;

    // ---- stage Q (pre-scaled 1/8) as bf16 hi/lo ----
    const float* Qg = q + ((size_t)(b * L + q0)) * DDIM;
    #pragma unroll
    for (int j = 0; j < 4; ++j) {
        int id = tid + j * NTHR;              // 1024 float2
        int r = id >> 5, c = (id & 31) * 2;
        float2 x = *(const float2*)&Qg[r * DDIM + c];
        uint32_t hi, lo; split2(x.x * 0.125f, x.y * 0.125f, hi, lo);
        *(uint32_t*)(sm + SM_QHI + r * (SK*2) + c*2) = hi;
        *(uint32_t*)(sm + SM_QLO + r * (SK*2) + c*2) = lo;
    }
    __syncthreads();

    // ---- preload Q A-fragments ----
    uint32_t aH[4][4], aL[4][4];
    {
        int arow = wr*16 + l7 + (g & 1) * 8;
        int akoff = (g >> 1) * 8;
        #pragma unroll
        for (int ks = 0; ks < 4; ++ks) {
            uint32_t off = (uint32_t)(arow * SK + ks*16 + akoff) * 2;
            ldmx4(aH[ks], smb + SM_QHI + off);
            ldmx4(aL[ks], smb + SM_QLO + off);
        }
    }

    float lsumA = 0.f, lsumB = 0.f;
    const float* Kg = k + (size_t)b * L * DDIM;
    const int rowA = wr * 16 + (lane >> 2);
    const int rowB = rowA + 8;
    const size_t grA = (size_t)(b*L + q0 + rowA) * L;
    const size_t grB = (size_t)(b*L + q0 + rowB) * L;
    float* Ab = attn + ((size_t)(b * L + q0)) * L;

    const int str = tid >> 5;             // staging row base (0..7)
    const int stc = (tid & 31) * 2;       // staging col

    // prefetch K tile 0
    float2 kreg[8];
    #pragma unroll
    for (int j = 0; j < 8; ++j)
        kreg[j] = *(const float2*)&Kg[(size_t)(str + j*8) * DDIM + stc];

    // ============ GEMM 1: e = exp(mask(Q K^T / 8)) -> attn (unnormalized) ============
    for (int kt = 0; kt < 16; ++kt) {
        #pragma unroll
        for (int j = 0; j < 8; ++j) {
            uint32_t hi, lo; split2(kreg[j].x, kreg[j].y, hi, lo);
            *(uint32_t*)(sm + SM_KHI + (str + j*8) * (SK*2) + stc*2) = hi;
            *(uint32_t*)(sm + SM_KLO + (str + j*8) * (SK*2) + stc*2) = lo;
        }
        __syncthreads();

        // branch-free prefetch next K tile (wraps to 0, always in-bounds)
        {
            const int ktn = (kt + 1) & 15;
            const float* Kn = Kg + (size_t)ktn * 64 * DDIM;
            #pragma unroll
            for (int j = 0; j < 8; ++j)
                kreg[j] = *(const float2*)&Kn[(size_t)(str + j*8) * DDIM + stc];
        }
        // hoist this tile's mask loads — latency hides behind MMA phase
        int2 cmA[2], cmB[2];
        #pragma unroll
        for (int nf = 0; nf < 2; ++nf) {
            int col = kt*64 + wc*16 + nf*8 + (lane & 3)*2;
            cmA[nf] = *(const int2*)&mask[grA + col];
            cmB[nf] = *(const int2*)&mask[grB + col];
        }

        float c4[2][4];
        #pragma unroll
        for (int i = 0; i < 2; ++i)
            #pragma unroll
            for (int jj = 0; jj < 4; ++jj) c4[i][jj] = 0.f;

        const int brow = wc*16 + l7 + (g >> 1) * 8;
        const int bkoff = (g & 1) * 8;
        #pragma unroll
        for (int ks = 0; ks < 4; ++ks) {
            uint32_t off = (uint32_t)(brow * SK + ks*16 + bkoff) * 2;
            uint32_t bh[4], bl[4];
            ldmx4(bh, smb + SM_KHI + off);
            ldmx4(bl, smb + SM_KLO + off);
            mma16816(c4[0], aH[ks], bh[0], bh[1]);
            mma16816(c4[0], aL[ks], bh[0], bh[1]);
            mma16816(c4[0], aH[ks], bl[0], bl[1]);
            mma16816(c4[1], aH[ks], bh[2], bh[3]);
            mma16816(c4[1], aL[ks], bh[2], bh[3]);
            mma16816(c4[1], aH[ks], bl[2], bl[3]);
        }

        // epilogue: e = exp(s) (0 if masked), accumulate l, write e to attn
        #pragma unroll
        for (int nf = 0; nf < 2; ++nf) {
            int col = kt*64 + wc*16 + nf*8 + (lane & 3)*2;
            float e0 = cmA[nf].x ? 0.f : __expf(c4[nf][0]);
            float e1 = cmA[nf].y ? 0.f : __expf(c4[nf][1]);
            float e2 = cmB[nf].x ? 0.f : __expf(c4[nf][2]);
            float e3 = cmB[nf].y ? 0.f : __expf(c4[nf][3]);
            lsumA += e0 + e1;
            lsumB += e2 + e3;
            *(float2*)&attn[grA + col] = make_float2(e0, e1);
            *(float2*)&attn[grB + col] = make_float2(e2, e3);
        }
        __syncthreads();      // frag reads done before next STS overwrite
    }

    // ---- row-sum reduce ----
    lsumA += __shfl_xor_sync(0xffffffffu, lsumA, 1);
    lsumA += __shfl_xor_sync(0xffffffffu, lsumA, 2);
    lsumB += __shfl_xor_sync(0xffffffffu, lsumB, 1);
    lsumB += __shfl_xor_sync(0xffffffffu, lsumB, 2);
    if ((lane & 3) == 0) {
        RED[rowA*4 + wc] = lsumA;
        RED[rowB*4 + wc] = lsumB;
    }
    // prefetch V tile 0 + e tile 0 while reduction syncs drain
    const float* Vg = v + (size_t)b * L * DDIM;
    #pragma unroll
    for (int j = 0; j < 8; ++j)
        kreg[j] = *(const float2*)&Vg[(size_t)(str + j*8) * DDIM + stc];
    const int pr  = tid >> 3;             // 0..31
    const int pc8 = (tid & 7) * 8;        // 0..56
    float4 ereg[2];
    ereg[0] = __ldcg((const float4*)&Ab[(size_t)pr * L + pc8]);
    ereg[1] = __ldcg((const float4*)&Ab[(size_t)pr * L + pc8 + 4]);
    __syncthreads();
    if (tid < 32) {
        float s4 = RED[tid*4] + RED[tid*4+1] + RED[tid*4+2] + RED[tid*4+3];
        ILrow[tid] = 1.f / s4;
    }
    __syncthreads();

    // =========================== GEMM 2: O = P V ===========================
    float o[2][4];
    #pragma unroll
    for (int i = 0; i < 2; ++i)
        #pragma unroll
        for (int jj = 0; jj < 4; ++jj) o[i][jj] = 0.f;

    for (int kt = 0; kt < 16; ++kt) {
        #pragma unroll
        for (int j = 0; j < 8; ++j) {
            uint32_t hi, lo; split2(kreg[j].x, kreg[j].y, hi, lo);
            *(uint32_t*)(sm + SM_KHI + (str + j*8) * (SK*2) + stc*2) = hi;
            *(uint32_t*)(sm + SM_KLO + (str + j*8) * (SK*2) + stc*2) = lo;
        }
        // stage P: p = e * il, overwrite attn with p, split to smem
        {
            float il = ILrow[pr];
            float p0 = ereg[0].x * il, p1 = ereg[0].y * il;
            float p2 = ereg[0].z * il, p3 = ereg[0].w * il;
            float p4 = ereg[1].x * il, p5 = ereg[1].y * il;
            float p6 = ereg[1].z * il, p7 = ereg[1].w * il;
            *(float4*)&Ab[(size_t)pr * L + kt*64 + pc8]     = make_float4(p0, p1, p2, p3);
            *(float4*)&Ab[(size_t)pr * L + kt*64 + pc8 + 4] = make_float4(p4, p5, p6, p7);
            uint32_t h0,l0,h1,l1,h2,l2,h3,l3;
            split2(p0, p1, h0, l0);
            split2(p2, p3, h1, l1);
            split2(p4, p5, h2, l2);
            split2(p6, p7, h3, l3);
            uint32_t off = (uint32_t)(pr * (SK*2) + pc8*2);
            *(uint4*)(sm + SM_PHI + off) = make_uint4(h0, h1, h2, h3);
            *(uint4*)(sm + SM_PLO + off) = make_uint4(l0, l1, l2, l3);
        }
        __syncthreads();

        // branch-free prefetch next V tile + next e tile
        {
            const int ktn = (kt + 1) & 15;
            const float* Vn = Vg + (size_t)ktn * 64 * DDIM;
            #pragma unroll
            for (int j = 0; j < 8; ++j)
                kreg[j] = *(const float2*)&Vn[(size_t)(str + j*8) * DDIM + stc];
            ereg[0] = __ldcg((const float4*)&Ab[(size_t)pr * L + ktn*64 + pc8]);
            ereg[1] = __ldcg((const float4*)&Ab[(size_t)pr * L + ktn*64 + pc8 + 4]);
        }

        const int arow = wr*16 + l7 + (g & 1) * 8, akoff = (g >> 1) * 8;
        const int vrow = l7 + (g & 1) * 8,  vnoff = (g >> 1) * 8;
        #pragma unroll
        for (int ks = 0; ks < 4; ++ks) {
            uint32_t pH[4], pL[4], vh[4], vl[4];
            uint32_t aoff = (uint32_t)(arow * SK + ks*16 + akoff) * 2;
            ldmx4(pH, smb + SM_PHI + aoff);
            ldmx4(pL, smb + SM_PLO + aoff);
            uint32_t boff = (uint32_t)((ks*16 + vrow) * SK + wc*16 + vnoff) * 2;
            ldmx4t(vh, smb + SM_KHI + boff);
            ldmx4t(vl, smb + SM_KLO + boff);
            mma16816(o[0], pH, vh[0], vh[1]);
            mma16816(o[0], pL, vh[0], vh[1]);
            mma16816(o[0], pH, vl[0], vl[1]);
            mma16816(o[1], pH, vh[2], vh[3]);
            mma16816(o[1], pL, vh[2], vh[3]);
            mma16816(o[1], pH, vl[2], vl[3]);
        }
        __syncthreads();
    }

    // ---- write O ----
    #pragma unroll
    for (int nf = 0; nf < 2; ++nf) {
        int col = wc*16 + nf*8 + (lane & 3)*2;
        *(float2*)&out[((size_t)(b*L + q0 + rowA))*DDIM + col] = make_float2(o[nf][0], o[nf][1]);
        *(float2*)&out[((size_t)(b*L + q0 + rowB))*DDIM + col] = make_float2(o[nf][2], o[nf][3]);
    }
}

extern "C" void kernel_launch(void* const* d_in, const int* in_sizes, int n_in,
                              void* d_out, int out_size)
{
    (void)in_sizes; (void)n_in; (void)out_size;
    const float* q = (const float*)d_in[0];
    const float* k = (const float*)d_in[1];
    const float* v = (const float*)d_in[2];
    const int*   mask = (const int*)d_in[3];

    float* outp = (float*)d_out;                            // [B, LQ, DD]
    float* attn = outp + (size_t)BATCH * L * DDIM;          // [B, LQ, LK]

    cudaFuncSetAttribute(sdpa_mma_kernel,
                         cudaFuncAttributeMaxDynamicSharedMemorySize, SM_TOT);

    dim3 grid(BATCH * (L / BM));    // 2048
    sdpa_mma_kernel<<<grid, NTHR, SM_TOT>>>(q, k, v, mask, outp, attn);
}

// round 14
// speedup vs baseline: 3.7845x; 1.1938x over previous
#include <cuda_runtime.h>
#include <cuda_bf16.h>
#include <cstdint>
#include <math.h>

#define DI __device__ __forceinline__

#define BATCH 64
#define L     1024
#define DDIM  64
#define BM    32
#define NTHR  256
#define SK    72            // smem row stride (halves)

// smem byte offsets (16B aligned) — 46720 B total => 2 CTAs/SM
#define SM_QHI  0           // 32*144 = 4608
#define SM_QLO  4608
#define SM_KHI  9216        // 64*144 = 9216
#define SM_KLO  18432
#define SM_VHI  27648
#define SM_VLO  36864
#define SM_OP   9216        // reused AFTER main loop: 8 warps x 16 x 64 floats = 32768
#define SM_RED  46080       // float[32][4]
#define SM_IL   46592       // float[32]
#define SM_TOT  46720

DI uint32_t smem_u32(const void* p){ uint32_t a;
  asm("{ .reg .u64 t; cvta.to.shared.u64 t, %1; cvt.u32.u64 %0, t; }":"=r"(a):"l"(p)); return a; }

DI void split2(float x, float y, uint32_t& hi, uint32_t& lo){
  __nv_bfloat16 hx = __float2bfloat16_rn(x), hy = __float2bfloat16_rn(y);
  float rx = x - __bfloat162float(hx), ry = y - __bfloat162float(hy);
  __nv_bfloat162 H; H.x = hx; H.y = hy;
  __nv_bfloat162 L2 = __floats2bfloat162_rn(rx, ry);
  hi = *reinterpret_cast<uint32_t*>(&H);
  lo = *reinterpret_cast<uint32_t*>(&L2);
}

DI void ldmx4(uint32_t* r, uint32_t addr){
  asm volatile("ldmatrix.sync.aligned.m8n8.x4.shared.b16 {%0,%1,%2,%3}, [%4];"
    : "=r"(r[0]),"=r"(r[1]),"=r"(r[2]),"=r"(r[3]) : "r"(addr));
}
DI void ldmx4t(uint32_t* r, uint32_t addr){
  asm volatile("ldmatrix.sync.aligned.m8n8.x4.trans.shared.b16 {%0,%1,%2,%3}, [%4];"
    : "=r"(r[0]),"=r"(r[1]),"=r"(r[2]),"=r"(r[3]) : "r"(addr));
}
DI void mma16816(float* c, const uint32_t* a, uint32_t b0, uint32_t b1){
  asm volatile("mma.sync.aligned.m16n8k16.row.col.f32.bf16.bf16.f32 "
    "{%0,%1,%2,%3}, {%4,%5,%6,%7}, {%8,%9}, {%0,%1,%2,%3};"
    : "+f"(c[0]),"+f"(c[1]),"+f"(c[2]),"+f"(c[3])
    : "r"(a[0]),"r"(a[1]),"r"(a[2]),"r"(a[3]), "r"(b0),"r"(b1));
}

__global__ void __launch_bounds__(NTHR, 2)
sdpa_mma_kernel(const float* __restrict__ q, const float* __restrict__ k,
                const float* __restrict__ v, const int* __restrict__ mask,
                float* __restrict__ out, float* __restrict__ attn)
{
    extern __shared__ char sm[];
    const uint32_t smb = smem_u32(sm);
    float* RED   = (float*)(sm + SM_RED);
    float* ILrow = (float*)(sm + SM_IL);

    const int tid  = threadIdx.x;
    const int wid  = tid >> 5, lane = tid & 31;
    const int wr   = wid >> 2, wc = wid & 3;    // 2 x 4 warp grid
    const int g    = lane >> 3, l7 = lane & 7;
    const int b    = blockIdx.x >> 5;
    const int q0   = (blockIdx.x & 31) * BM;

    // ---- stage Q (pre-scaled 1/8) as bf16 hi/lo ----
    const float* Qg = q + ((size_t)(b * L + q0)) * DDIM;
    #pragma unroll
    for (int j = 0; j < 4; ++j) {
        int id = tid + j * NTHR;              // 1024 float2
        int r = id >> 5, c = (id & 31) * 2;
        float2 x = *(const float2*)&Qg[r * DDIM + c];
        uint32_t hi, lo; split2(x.x * 0.125f, x.y * 0.125f, hi, lo);
        *(uint32_t*)(sm + SM_QHI + r * (SK*2) + c*2) = hi;
        *(uint32_t*)(sm + SM_QLO + r * (SK*2) + c*2) = lo;
    }
    __syncthreads();

    // ---- preload Q A-fragments ----
    uint32_t aH[4][4], aL[4][4];
    {
        int arow = wr*16 + l7 + (g & 1) * 8;
        int akoff = (g >> 1) * 8;
        #pragma unroll
        for (int ks = 0; ks < 4; ++ks) {
            uint32_t off = (uint32_t)(arow * SK + ks*16 + akoff) * 2;
            ldmx4(aH[ks], smb + SM_QHI + off);
            ldmx4(aL[ks], smb + SM_QLO + off);
        }
    }

    float lsumA = 0.f, lsumB = 0.f;
    const float* Kg = k + (size_t)b * L * DDIM;
    const float* Vg = v + (size_t)b * L * DDIM;
    const int rowA = wr * 16 + (lane >> 2);
    const int rowB = rowA + 8;
    const size_t grA = (size_t)(b*L + q0 + rowA) * L;
    const size_t grB = (size_t)(b*L + q0 + rowB) * L;
    float* Ab = attn + ((size_t)(b * L + q0)) * L;

    // O accumulator: warp's key-slice partial, 16 q-rows x 64 d
    float o[8][4];
    #pragma unroll
    for (int f = 0; f < 8; ++f)
        #pragma unroll
        for (int jj = 0; jj < 4; ++jj) o[f][jj] = 0.f;

    // prefetch K/V tile 0 (float4 granularity: 64x64 tile, 4 per thread each)
    float4 kreg4[4], vreg4[4];
    #pragma unroll
    for (int j = 0; j < 4; ++j) {
        int id = tid + j * NTHR;              // 1024 float4
        int r = id >> 4, c = (id & 15) * 4;
        kreg4[j] = *(const float4*)&Kg[(size_t)r * DDIM + c];
        vreg4[j] = *(const float4*)&Vg[(size_t)r * DDIM + c];
    }

    // ==================== fused loop over 16 key tiles ====================
    for (int kt = 0; kt < 16; ++kt) {
        // stage K+V hi/lo (STS.64)
        #pragma unroll
        for (int j = 0; j < 4; ++j) {
            int id = tid + j * NTHR;
            int r = id >> 4, c = (id & 15) * 4;
            uint32_t off = (uint32_t)(r * (SK*2) + c*2);
            uint32_t h0,l0,h1,l1;
            split2(kreg4[j].x, kreg4[j].y, h0, l0);
            split2(kreg4[j].z, kreg4[j].w, h1, l1);
            *(uint2*)(sm + SM_KHI + off) = make_uint2(h0, h1);
            *(uint2*)(sm + SM_KLO + off) = make_uint2(l0, l1);
            split2(vreg4[j].x, vreg4[j].y, h0, l0);
            split2(vreg4[j].z, vreg4[j].w, h1, l1);
            *(uint2*)(sm + SM_VHI + off) = make_uint2(h0, h1);
            *(uint2*)(sm + SM_VLO + off) = make_uint2(l0, l1);
        }
        __syncthreads();

        // branch-free prefetch next tile (wraps to 0; always in-bounds)
        {
            const int ktn = (kt + 1) & 15;
            const float* Kn = Kg + (size_t)ktn * 64 * DDIM;
            const float* Vn = Vg + (size_t)ktn * 64 * DDIM;
            #pragma unroll
            for (int j = 0; j < 4; ++j) {
                int id = tid + j * NTHR;
                int r = id >> 4, c = (id & 15) * 4;
                kreg4[j] = *(const float4*)&Kn[(size_t)r * DDIM + c];
                vreg4[j] = *(const float4*)&Vn[(size_t)r * DDIM + c];
            }
        }
        // hoist this tile's mask loads
        int2 cmA[2], cmB[2];
        #pragma unroll
        for (int nf = 0; nf < 2; ++nf) {
            int col = kt*64 + wc*16 + nf*8 + (lane & 3)*2;
            cmA[nf] = *(const int2*)&mask[grA + col];
            cmB[nf] = *(const int2*)&mask[grB + col];
        }

        // ---- GEMM1: S slice = (Q/8) K^T  (16 q x 16 keys per warp) ----
        float c4[2][4];
        #pragma unroll
        for (int i = 0; i < 2; ++i)
            #pragma unroll
            for (int jj = 0; jj < 4; ++jj) c4[i][jj] = 0.f;

        const int brow = wc*16 + l7 + (g >> 1) * 8;
        const int bkoff = (g & 1) * 8;
        #pragma unroll
        for (int ks = 0; ks < 4; ++ks) {
            uint32_t off = (uint32_t)(brow * SK + ks*16 + bkoff) * 2;
            uint32_t bh[4], bl[4];
            ldmx4(bh, smb + SM_KHI + off);
            ldmx4(bl, smb + SM_KLO + off);
            mma16816(c4[0], aH[ks], bh[0], bh[1]);
            mma16816(c4[0], aL[ks], bh[0], bh[1]);
            mma16816(c4[0], aH[ks], bl[0], bl[1]);
            mma16816(c4[1], aH[ks], bh[2], bh[3]);
            mma16816(c4[1], aL[ks], bh[2], bh[3]);
            mma16816(c4[1], aH[ks], bl[2], bl[3]);
        }

        // ---- epilogue: e = exp(masked s); write e to attn; pack e as PV A-frags ----
        uint32_t eH[4], eL[4];
        #pragma unroll
        for (int nf = 0; nf < 2; ++nf) {
            int col = kt*64 + wc*16 + nf*8 + (lane & 3)*2;
            float e0 = cmA[nf].x ? 0.f : __expf(c4[nf][0]);
            float e1 = cmA[nf].y ? 0.f : __expf(c4[nf][1]);
            float e2 = cmB[nf].x ? 0.f : __expf(c4[nf][2]);
            float e3 = cmB[nf].y ? 0.f : __expf(c4[nf][3]);
            lsumA += e0 + e1;
            lsumB += e2 + e3;
            *(float2*)&attn[grA + col] = make_float2(e0, e1);
            *(float2*)&attn[grB + col] = make_float2(e2, e3);
            // accumulator -> A-fragment (a0:row r k0-7; a1:row r+8 k0-7; a2/a3: k8-15)
            split2(e0, e1, eH[nf*2 + 0], eL[nf*2 + 0]);
            split2(e2, e3, eH[nf*2 + 1], eL[nf*2 + 1]);
        }

        // ---- GEMM2: O += e_slice * V_slice  (k16 = warp's keys, n64 = d) ----
        const int vrow = l7 + (g & 1) * 8, vnoff = (g >> 1) * 8;
        #pragma unroll
        for (int nb = 0; nb < 4; ++nb) {
            uint32_t vh[4], vl[4];
            uint32_t boff = (uint32_t)((wc*16 + vrow) * SK + nb*16 + vnoff) * 2;
            ldmx4t(vh, smb + SM_VHI + boff);
            ldmx4t(vl, smb + SM_VLO + boff);
            mma16816(o[2*nb],   eH, vh[0], vh[1]);
            mma16816(o[2*nb],   eL, vh[0], vh[1]);
            mma16816(o[2*nb],   eH, vl[0], vl[1]);
            mma16816(o[2*nb+1], eH, vh[2], vh[3]);
            mma16816(o[2*nb+1], eL, vh[2], vh[3]);
            mma16816(o[2*nb+1], eH, vl[2], vl[3]);
        }
        __syncthreads();      // frag/V reads done before next STS overwrite
    }

    // ---- row-sum partials + O partials to smem (K/V region now dead) ----
    lsumA += __shfl_xor_sync(0xffffffffu, lsumA, 1);
    lsumA += __shfl_xor_sync(0xffffffffu, lsumA, 2);
    lsumB += __shfl_xor_sync(0xffffffffu, lsumB, 1);
    lsumB += __shfl_xor_sync(0xffffffffu, lsumB, 2);
    if ((lane & 3) == 0) {
        RED[rowA*4 + wc] = lsumA;
        RED[rowB*4 + wc] = lsumB;
    }
    {
        float* OPw = (float*)(sm + SM_OP) + wid * 16 * 64;
        int r0 = lane >> 2;
        #pragma unroll
        for (int f = 0; f < 8; ++f) {
            int c = f*8 + (lane & 3)*2;
            *(float2*)&OPw[r0*64 + c]      = make_float2(o[f][0], o[f][1]);
            *(float2*)&OPw[(r0+8)*64 + c]  = make_float2(o[f][2], o[f][3]);
        }
    }
    __syncthreads();
    if (tid < 32) {
        float s4 = RED[tid*4] + RED[tid*4+1] + RED[tid*4+2] + RED[tid*4+3];
        ILrow[tid] = 1.f / s4;
    }
    __syncthreads();

    // ---- finalize O: sum 4 key-slice partials, scale by 1/l ----
    {
        int r = tid >> 3, cg = (tid & 7) * 8;
        float il = ILrow[r];
        const float* OP = (const float*)(sm + SM_OP);
        float a0=0,a1=0,a2=0,a3=0,a4=0,a5=0,a6=0,a7=0;
        #pragma unroll
        for (int wcx = 0; wcx < 4; ++wcx) {
            int base = (((r >> 4)*4 + wcx)*16 + (r & 15))*64 + cg;
            float4 u0 = *(const float4*)&OP[base];
            float4 u1 = *(const float4*)&OP[base + 4];
            a0 += u0.x; a1 += u0.y; a2 += u0.z; a3 += u0.w;
            a4 += u1.x; a5 += u1.y; a6 += u1.z; a7 += u1.w;
        }
        float* orow = out + ((size_t)(b*L + q0 + r)) * DDIM + cg;
        *(float4*)&orow[0] = make_float4(a0*il, a1*il, a2*il, a3*il);
        *(float4*)&orow[4] = make_float4(a4*il, a5*il, a6*il, a7*il);
    }

    // ---- streaming attn rescale: p = e * il ----
    #pragma unroll 4
    for (int j = 0; j < 32; ++j) {
        int id = tid + j * NTHR;             // 8192 float4 over 32x1024
        int r = id >> 8, ci = (id & 255) * 4;
        float il = ILrow[r];
        float4 t = *(const float4*)&Ab[(size_t)r * L + ci];
        t.x *= il; t.y *= il; t.z *= il; t.w *= il;
        *(float4*)&Ab[(size_t)r * L + ci] = t;
    }
}

extern "C" void kernel_launch(void* const* d_in, const int* in_sizes, int n_in,
                              void* d_out, int out_size)
{
    (void)in_sizes; (void)n_in; (void)out_size;
    const float* q = (const float*)d_in[0];
    const float* k = (const float*)d_in[1];
    const float* v = (const float*)d_in[2];
    const int*   mask = (const int*)d_in[3];

    float* outp = (float*)d_out;                            // [B, LQ, DD]
    float* attn = outp + (size_t)BATCH * L * DDIM;          // [B, LQ, LK]

    cudaFuncSetAttribute(sdpa_mma_kernel,
                         cudaFuncAttributeMaxDynamicSharedMemorySize, SM_TOT);

    dim3 grid(BATCH * (L / BM));    // 2048
    sdpa_mma_kernel<<<grid, NTHR, SM_TOT>>>(q, k, v, mask, outp, attn);
}